// round 9
// baseline (speedup 1.0000x reference)
#include <cuda_runtime.h>
#include <math.h>

// ---------------------------------------------------------------------------
// Problem constants: B=128, T=1024, D=512, H=512, 4H=2048
//   0: sequence_tensor f32 [128,1024,512]
//   1: batch_lengths   int32 (JAX x64 off) or int64 [128], sorted descending
//   2: W_ih f32 [2048,512]   3: W_hh f32 [2048,512]
//   4: b_ih f32 [2048]       5: b_hh f32 [2048]
// Output: concat( out[128,1024,512], h_final[1,128,512], c_final[1,128,512] )
// ---------------------------------------------------------------------------

#define Bsz   128
#define Tsz   1024
#define Dsz   512
#define Hsz   512
#define G4    2048
#define HPAD  516   // padded smem row stride (floats): rows stagger 4 banks

// Scratch: precomputed input gates  G[t][b][j]  (1 GiB)
__device__ float g_G[(size_t)Tsz * Bsz * G4];
// Double-buffered hidden state h[b][k]
__device__ float g_hbuf[2][Bsz * Hsz];
// Per-btile barrier state (4 btiles, 128B-padded lines)
__device__ __align__(128) unsigned g_bar_cnt4[4][32];
__device__ __align__(128) unsigned g_bar_gen4[4][32];

// ---- packed fp32 helpers (FFMA2 path: PTX fma.rn.f32x2) --------------------
__device__ __forceinline__ unsigned long long pack2(float x, float y) {
    unsigned long long r;
    asm("mov.b64 %0, {%1, %2};" : "=l"(r) : "f"(x), "f"(y));
    return r;
}
__device__ __forceinline__ void unpack2(unsigned long long v, float& x, float& y) {
    asm("mov.b64 {%0, %1}, %2;" : "=f"(x), "=f"(y) : "l"(v));
}
#define FMA2(d, a, b) asm("fma.rn.f32x2 %0, %1, %2, %0;" : "+l"(d) : "l"(a), "l"(b))

// ---- scoped atomics for the software barrier --------------------------------
__device__ __forceinline__ unsigned ld_acquire_gpu(unsigned* p) {
    unsigned v;
    asm volatile("ld.acquire.gpu.u32 %0, [%1];" : "=r"(v) : "l"(p) : "memory");
    return v;
}
__device__ __forceinline__ unsigned ld_relaxed_gpu(unsigned* p) {
    unsigned v;
    asm volatile("ld.relaxed.gpu.u32 %0, [%1];" : "=r"(v) : "l"(p) : "memory");
    return v;
}
__device__ __forceinline__ unsigned atom_add_acqrel_gpu(unsigned* p, unsigned v) {
    unsigned o;
    asm volatile("atom.add.acq_rel.gpu.u32 %0, [%1], %2;"
                 : "=r"(o) : "l"(p), "r"(v) : "memory");
    return o;
}
__device__ __forceinline__ void st_release_gpu(unsigned* p, unsigned v) {
    asm volatile("st.release.gpu.u32 [%0], %1;" :: "l"(p), "r"(v) : "memory");
}
__device__ __forceinline__ void st_relaxed_gpu(unsigned* p, unsigned v) {
    asm volatile("st.relaxed.gpu.u32 [%0], %1;" :: "l"(p), "r"(v) : "memory");
}

// ---- length dtype detection (int32 vs int64) --------------------------------
__device__ __forceinline__ bool lens_is64(const int* p) {
    return (p[1] == 0 && p[3] == 0 && p[5] == 0);
}
__device__ __forceinline__ int load_len(const int* p, bool is64, int b) {
    return is64 ? p[2 * b] : p[b];
}

// ---------------------------------------------------------------------------
// Phase 1: G[t][b][j] = sum_k seq[b][t][k] * W_ih[j][k] + (b_ih[j] + b_hh[j])
// 128x128x16 SGEMM per block, FFMA2 inner product.  Measured at ~93% of its
// FFMA2 pipe floor — unchanged.
// ---------------------------------------------------------------------------
__global__ void __launch_bounds__(256) pregemm_kernel(
    const float* __restrict__ seq,
    const float* __restrict__ Wih,
    const float* __restrict__ bih,
    const float* __restrict__ bhh,
    const int*   __restrict__ lensraw)
{
    __shared__ float As[16][128];
    __shared__ float Bs[16][128];

    const int t   = blockIdx.y;
    const int j0  = blockIdx.x * 128;
    const int tid = threadIdx.x;
    const int tx  = tid & 15;
    const int ty  = tid >> 4;

    const bool is64 = lens_is64(lensraw);
    const bool grpActive = (load_len(lensraw, is64, ty * 8) > t);

    unsigned long long acc2[8][4];
#pragma unroll
    for (int p = 0; p < 4; ++p) {
        const int j = j0 + tx * 8 + 2 * p;
        const unsigned long long bv =
            pack2(bih[j] + bhh[j], bih[j + 1] + bhh[j + 1]);
#pragma unroll
        for (int i = 0; i < 8; ++i) acc2[i][p] = bv;
    }

    const int lm = tid >> 1;
    const int lk = (tid & 1) * 8;
    const float* arow = seq + ((size_t)lm * Tsz + t) * Dsz + lk;
    const float* brow = Wih + (size_t)(j0 + lm) * Dsz + lk;

    for (int k0 = 0; k0 < Dsz; k0 += 16) {
        const float4 av0 = *(const float4*)(arow + k0);
        const float4 av1 = *(const float4*)(arow + k0 + 4);
        const float4 bv0 = *(const float4*)(brow + k0);
        const float4 bv1 = *(const float4*)(brow + k0 + 4);
        As[lk + 0][lm] = av0.x; As[lk + 1][lm] = av0.y;
        As[lk + 2][lm] = av0.z; As[lk + 3][lm] = av0.w;
        As[lk + 4][lm] = av1.x; As[lk + 5][lm] = av1.y;
        As[lk + 6][lm] = av1.z; As[lk + 7][lm] = av1.w;
        Bs[lk + 0][lm] = bv0.x; Bs[lk + 1][lm] = bv0.y;
        Bs[lk + 2][lm] = bv0.z; Bs[lk + 3][lm] = bv0.w;
        Bs[lk + 4][lm] = bv1.x; Bs[lk + 5][lm] = bv1.y;
        Bs[lk + 6][lm] = bv1.z; Bs[lk + 7][lm] = bv1.w;
        __syncthreads();

        if (grpActive) {
#pragma unroll
            for (int kk = 0; kk < 16; ++kk) {
                const float4 a0 = *(const float4*)&As[kk][ty * 8];
                const float4 a1 = *(const float4*)&As[kk][ty * 8 + 4];
                const ulonglong2 bb0 = *(const ulonglong2*)&Bs[kk][tx * 8];
                const ulonglong2 bb1 = *(const ulonglong2*)&Bs[kk][tx * 8 + 4];
                const float a[8] = {a0.x, a0.y, a0.z, a0.w,
                                    a1.x, a1.y, a1.z, a1.w};
#pragma unroll
                for (int i = 0; i < 8; ++i) {
                    const unsigned long long ad = pack2(a[i], a[i]);
                    FMA2(acc2[i][0], ad, bb0.x);
                    FMA2(acc2[i][1], ad, bb0.y);
                    FMA2(acc2[i][2], ad, bb1.x);
                    FMA2(acc2[i][3], ad, bb1.y);
                }
            }
        }
        __syncthreads();
    }

    if (grpActive) {
#pragma unroll
        for (int i = 0; i < 8; ++i) {
            float f0, f1, f2, f3, f4, f5, f6, f7;
            unpack2(acc2[i][0], f0, f1);
            unpack2(acc2[i][1], f2, f3);
            unpack2(acc2[i][2], f4, f5);
            unpack2(acc2[i][3], f6, f7);
            const size_t o = ((size_t)t * Bsz + ty * 8 + i) * G4 + j0 + tx * 8;
            *(float4*)&g_G[o]     = make_float4(f0, f1, f2, f3);
            *(float4*)&g_G[o + 4] = make_float4(f4, f5, f6, f7);
        }
    }
}

// ---------------------------------------------------------------------------
// Per-btile software barrier (32 blocks), release/acquire atomics only.
// ---------------------------------------------------------------------------
__device__ __forceinline__ void tile_barrier(unsigned* cnt, unsigned* gen)
{
    __syncthreads();
    if (threadIdx.x == 0) {
        const unsigned old = ld_relaxed_gpu(gen);
        const unsigned ticket = atom_add_acqrel_gpu(cnt, 1u);
        if (ticket == 31u) {
            st_relaxed_gpu(cnt, 0u);
            st_release_gpu(gen, old + 1u);
        } else {
            while (ld_acquire_gpu(gen) == old) { }
        }
    }
    __syncthreads();
}

__device__ __forceinline__ float sigmf(float x) {
    return __fdividef(1.f, 1.f + __expf(-x));
}
__device__ __forceinline__ float tanh_fast(float x) {
    return 1.f - __fdividef(2.f, __expf(2.f * x) + 1.f);
}

// ---------------------------------------------------------------------------
// Phase 2: persistent recurrence, 512 threads/block (16 warps, 4/SMSP).
// 128 blocks = (btile 0..3 [32 rows]) x (ntile 0..31 [16 hidden units]).
// Warp tile 4 rows x 8 units: warp_r = wid&7, warp_c = wid>>3;
// lane_r = lid>>3 (row), lane_c = lid&7 (unit).  Thread = ONE (row, unit)
// pair, all 4 gates -> thread-local LSTM update, c/h state in registers.
// smem: W_s[gate*16+nhl][k] (64 x HPAD), h_s[b][k] (32 x HPAD); both direct
// row copies.  Accumulator lanes = (even-k, odd-k) partial sums.
// ---------------------------------------------------------------------------
__global__ void __launch_bounds__(512, 1) lstm_steps_kernel(
    const float* __restrict__ Whh,
    const int*   __restrict__ lensraw,
    float* __restrict__ out,    // [B,T,H]
    float* __restrict__ hfin,   // [B,H]
    float* __restrict__ cfin)   // [B,H]
{
    extern __shared__ float sm[];
    float* W_s = sm;                   // 64 x HPAD
    float* h_s = sm + 64 * HPAD;       // 32 x HPAD

    const int tid   = threadIdx.x;         // 0..511
    const int bx    = blockIdx.x;          // 0..127
    const int ntile = bx & 31;
    const int btile = bx >> 5;
    const int n0    = ntile * 16;
    const int b0    = btile * 32;
    unsigned* bar_cnt = &g_bar_cnt4[btile][0];
    unsigned* bar_gen = &g_bar_gen4[btile][0];

    // ---- stage W_hh (once): W_s[gate*16 + nhl][k] = Whh[gate*512 + n0+nhl][k]
    {
        const int rc    = tid >> 3;             // 0..63
        const int chunk = tid & 7;              // 0..7 (64 floats each)
        const int gate  = rc >> 4;
        const int nhl   = rc & 15;
        const float* src = Whh + (size_t)(gate * Hsz + n0 + nhl) * Hsz + chunk * 64;
        float* dst = W_s + rc * HPAD + chunk * 64;
#pragma unroll
        for (int i = 0; i < 16; ++i)
            *(float4*)(dst + i * 4) = *(const float4*)(src + i * 4);
    }
    // ---- zero this block's slice of hbuf[0]  (32 rows x 16 cols = 512)
    {
        const int r = tid >> 4, cc = tid & 15;
        g_hbuf[0][(size_t)(b0 + r) * Hsz + n0 + cc] = 0.f;
    }
    // ---- zero-fill out for this btile: rows [b0,b0+32), t in [ntile*32,+32)
    {
        const float4 z4 = make_float4(0.f, 0.f, 0.f, 0.f);
        for (int it = 0; it < 256; ++it) {
            const int idx = it * 512 + tid;       // float4 index 0..131071
            const int bt  = idx >> 7;             // (b,t) pair 0..1023
            const int f4  = idx & 127;
            const int r   = bt >> 5;
            const int tt  = ntile * 32 + (bt & 31);
            float4* dst = (float4*)(out + ((size_t)(b0 + r) * Tsz + tt) * Hsz);
            dst[f4] = z4;
        }
    }
    tile_barrier(bar_cnt, bar_gen);

    // ---- GEMM thread mapping: warp tile 4 rows x 8 units
    const int wid    = tid >> 5;
    const int lid    = tid & 31;
    const int warp_r = wid & 7;                 // 8 row groups of 4
    const int warp_c = wid >> 3;                // 2 unit groups of 8
    const int lane_r = lid >> 3;                // 0..3
    const int lane_c = lid & 7;                 // 0..7
    const int bloc   = warp_r * 4 + lane_r;     // local row 0..31
    const int b_r    = b0 + bloc;
    const int nh     = warp_c * 8 + lane_c;     // 0..15
    const int n      = n0 + nh;

    const bool is64 = lens_is64(lensraw);
    const int len_tile = load_len(lensraw, is64, b0);
    const int len_r    = load_len(lensraw, is64, b_r);

    float hprev = 0.f, creg = 0.f;

    const float* hp  = h_s + bloc * HPAD;
    const float* wp0 = W_s + (0 * 16 + nh) * HPAD;  // gate i
    const float* wp1 = W_s + (1 * 16 + nh) * HPAD;  // gate f
    const float* wp2 = W_s + (2 * 16 + nh) * HPAD;  // gate g
    const float* wp3 = W_s + (3 * 16 + nh) * HPAD;  // gate o

    // staging mapping: row = tid>>4 (0..31), 32-float chunk = (tid&15)*32
    const int st_row = tid >> 4;
    const int st_off = (tid & 15) * 32;
    float* st_dst = h_s + st_row * HPAD + st_off;

#pragma unroll 1
    for (int t = 0; t < Tsz; ++t) {
        float* hnext = g_hbuf[(t + 1) & 1];
        const bool tileActive = (t < len_tile);

        if (tileActive) {
            // -- prefetch G[t] (DRAM, independent of h)
            const float* gr = g_G + ((size_t)t * Bsz + b_r) * G4 + n;
            const float gi = __ldcg(gr);
            const float gf = __ldcg(gr + 512);
            const float gg = __ldcg(gr + 1024);
            const float go = __ldcg(gr + 1536);

            // -- stage h tile (direct row copy, L2-coherent)
            {
                const float* src = g_hbuf[t & 1] +
                                   (size_t)(b0 + st_row) * Hsz + st_off;
#pragma unroll
                for (int i = 0; i < 8; ++i)
                    *(float4*)(st_dst + i * 4) =
                        __ldcg((const float4*)(src + i * 4));
            }
            __syncthreads();

            // -- k-SIMD micro-GEMM: 4 gate dots, acc lanes = (even-k, odd-k)
            unsigned long long A0 = 0ull, A1 = 0ull, A2 = 0ull, A3 = 0ull;
#pragma unroll 8
            for (int k = 0; k < Hsz; k += 4) {
                const ulonglong2 hv = *(const ulonglong2*)(hp + k);
                const ulonglong2 w0 = *(const ulonglong2*)(wp0 + k);
                const ulonglong2 w1 = *(const ulonglong2*)(wp1 + k);
                const ulonglong2 w2 = *(const ulonglong2*)(wp2 + k);
                const ulonglong2 w3 = *(const ulonglong2*)(wp3 + k);
                FMA2(A0, hv.x, w0.x); FMA2(A0, hv.y, w0.y);
                FMA2(A1, hv.x, w1.x); FMA2(A1, hv.y, w1.y);
                FMA2(A2, hv.x, w2.x); FMA2(A2, hv.y, w2.y);
                FMA2(A3, hv.x, w3.x); FMA2(A3, hv.y, w3.y);
            }
            float e, o2;
            unpack2(A0, e, o2); const float ai = e + o2;
            unpack2(A1, e, o2); const float af = e + o2;
            unpack2(A2, e, o2); const float ag = e + o2;
            unpack2(A3, e, o2); const float ao = e + o2;

            // -- elementwise LSTM update
            const float iv = sigmf(ai + gi);
            const float fv = sigmf(af + gf);
            const float gv = tanh_fast(ag + gg);
            const float ov = sigmf(ao + go);
            const float cn = fv * creg + iv * gv;
            const float hn = ov * tanh_fast(cn);
            const bool act = (t < len_r);
            creg  = act ? cn : creg;
            hprev = act ? hn : hprev;
            if (act) out[((size_t)b_r * Tsz + t) * Hsz + n] = hn;
            hnext[(size_t)b_r * Hsz + n] = hprev;
        }
        // inactive tile: outputs already zero-filled, h frozen

        tile_barrier(bar_cnt, bar_gen);   // h handoff within this btile
    }

    // final (frozen) states
    hfin[(size_t)b_r * Hsz + n] = hprev;
    cfin[(size_t)b_r * Hsz + n] = creg;
}

// ---------------------------------------------------------------------------
extern "C" void kernel_launch(void* const* d_in, const int* in_sizes, int n_in,
                              void* d_out, int out_size)
{
    (void)in_sizes; (void)n_in; (void)out_size;
    const float* seq  = (const float*)d_in[0];
    const int*   lens = (const int*)d_in[1];
    const float* Wih  = (const float*)d_in[2];
    const float* Whh  = (const float*)d_in[3];
    const float* bih  = (const float*)d_in[4];
    const float* bhh  = (const float*)d_in[5];

    float* outp = (float*)d_out;
    float* hfin = outp + (size_t)Bsz * Tsz * Hsz;
    float* cfin = hfin + (size_t)Bsz * Hsz;

    // dynamic smem: (64 + 32) * HPAD * 4 = 198,144 B
    const int smem_bytes = (64 + 32) * HPAD * 4;
    cudaFuncSetAttribute(lstm_steps_kernel,
                         cudaFuncAttributeMaxDynamicSharedMemorySize, smem_bytes);

    // Phase 1: input-gate GEMM  (16 column tiles x 1024 timesteps)
    dim3 grid1(G4 / 128, Tsz);
    pregemm_kernel<<<grid1, 256>>>(seq, Wih, bih, bhh, lens);

    // Phase 2: persistent recurrence (128 co-resident blocks, btile barriers)
    lstm_steps_kernel<<<128, 512, smem_bytes>>>(Whh, lens, outp, hfin, cfin);
}

// round 10
// speedup vs baseline: 1.4204x; 1.4204x over previous
#include <cuda_runtime.h>
#include <math.h>

// ---------------------------------------------------------------------------
// Problem constants: B=128, T=1024, D=512, H=512, 4H=2048
//   0: sequence_tensor f32 [128,1024,512]
//   1: batch_lengths   int32 (JAX x64 off) or int64 [128], sorted descending
//   2: W_ih f32 [2048,512]   3: W_hh f32 [2048,512]
//   4: b_ih f32 [2048]       5: b_hh f32 [2048]
// Output: concat( out[128,1024,512], h_final[1,128,512], c_final[1,128,512] )
// ---------------------------------------------------------------------------

#define Bsz   128
#define Tsz   1024
#define Dsz   512
#define Hsz   512
#define G4    2048
#define PPITCH 68   // gate-partial smem row pitch (floats): 17 mod 32 -> conflict-free

// Scratch: precomputed input gates  G[t][b][j]  (1 GiB)
__device__ float g_G[(size_t)Tsz * Bsz * G4];
// Double-buffered hidden state h[b][k]
__device__ float g_hbuf[2][Bsz * Hsz];
// Per-btile barrier state (4 btiles, 128B-padded lines)
__device__ __align__(128) unsigned g_bar_cnt4[4][32];
__device__ __align__(128) unsigned g_bar_gen4[4][32];

// ---- packed fp32 helpers (FFMA2 path: PTX fma.rn.f32x2) --------------------
__device__ __forceinline__ unsigned long long pack2(float x, float y) {
    unsigned long long r;
    asm("mov.b64 %0, {%1, %2};" : "=l"(r) : "f"(x), "f"(y));
    return r;
}
__device__ __forceinline__ void unpack2(unsigned long long v, float& x, float& y) {
    asm("mov.b64 {%0, %1}, %2;" : "=f"(x), "=f"(y) : "l"(v));
}
#define FMA2(d, a, b) asm("fma.rn.f32x2 %0, %1, %2, %0;" : "+l"(d) : "l"(a), "l"(b))

// ---- scoped atomics for the software barrier --------------------------------
__device__ __forceinline__ unsigned ld_acquire_gpu(unsigned* p) {
    unsigned v;
    asm volatile("ld.acquire.gpu.u32 %0, [%1];" : "=r"(v) : "l"(p) : "memory");
    return v;
}
__device__ __forceinline__ unsigned ld_relaxed_gpu(unsigned* p) {
    unsigned v;
    asm volatile("ld.relaxed.gpu.u32 %0, [%1];" : "=r"(v) : "l"(p) : "memory");
    return v;
}
__device__ __forceinline__ unsigned atom_add_acqrel_gpu(unsigned* p, unsigned v) {
    unsigned o;
    asm volatile("atom.add.acq_rel.gpu.u32 %0, [%1], %2;"
                 : "=r"(o) : "l"(p), "r"(v) : "memory");
    return o;
}
__device__ __forceinline__ void st_release_gpu(unsigned* p, unsigned v) {
    asm volatile("st.release.gpu.u32 [%0], %1;" :: "l"(p), "r"(v) : "memory");
}
__device__ __forceinline__ void st_relaxed_gpu(unsigned* p, unsigned v) {
    asm volatile("st.relaxed.gpu.u32 [%0], %1;" :: "l"(p), "r"(v) : "memory");
}

// ---- length dtype detection (int32 vs int64) --------------------------------
__device__ __forceinline__ bool lens_is64(const int* p) {
    return (p[1] == 0 && p[3] == 0 && p[5] == 0);
}
__device__ __forceinline__ int load_len(const int* p, bool is64, int b) {
    return is64 ? p[2 * b] : p[b];
}

// ---------------------------------------------------------------------------
// Phase 1: G[t][b][j] = sum_k seq[b][t][k] * W_ih[j][k] + (b_ih[j] + b_hh[j])
// 128x128x16 SGEMM per block, FFMA2.  ~93% of FFMA2 pipe floor — unchanged.
// ---------------------------------------------------------------------------
__global__ void __launch_bounds__(256) pregemm_kernel(
    const float* __restrict__ seq,
    const float* __restrict__ Wih,
    const float* __restrict__ bih,
    const float* __restrict__ bhh,
    const int*   __restrict__ lensraw)
{
    __shared__ float As[16][128];
    __shared__ float Bs[16][128];

    const int t   = blockIdx.y;
    const int j0  = blockIdx.x * 128;
    const int tid = threadIdx.x;
    const int tx  = tid & 15;
    const int ty  = tid >> 4;

    const bool is64 = lens_is64(lensraw);
    const bool grpActive = (load_len(lensraw, is64, ty * 8) > t);

    unsigned long long acc2[8][4];
#pragma unroll
    for (int p = 0; p < 4; ++p) {
        const int j = j0 + tx * 8 + 2 * p;
        const unsigned long long bv =
            pack2(bih[j] + bhh[j], bih[j + 1] + bhh[j + 1]);
#pragma unroll
        for (int i = 0; i < 8; ++i) acc2[i][p] = bv;
    }

    const int lm = tid >> 1;
    const int lk = (tid & 1) * 8;
    const float* arow = seq + ((size_t)lm * Tsz + t) * Dsz + lk;
    const float* brow = Wih + (size_t)(j0 + lm) * Dsz + lk;

    for (int k0 = 0; k0 < Dsz; k0 += 16) {
        const float4 av0 = *(const float4*)(arow + k0);
        const float4 av1 = *(const float4*)(arow + k0 + 4);
        const float4 bv0 = *(const float4*)(brow + k0);
        const float4 bv1 = *(const float4*)(brow + k0 + 4);
        As[lk + 0][lm] = av0.x; As[lk + 1][lm] = av0.y;
        As[lk + 2][lm] = av0.z; As[lk + 3][lm] = av0.w;
        As[lk + 4][lm] = av1.x; As[lk + 5][lm] = av1.y;
        As[lk + 6][lm] = av1.z; As[lk + 7][lm] = av1.w;
        Bs[lk + 0][lm] = bv0.x; Bs[lk + 1][lm] = bv0.y;
        Bs[lk + 2][lm] = bv0.z; Bs[lk + 3][lm] = bv0.w;
        Bs[lk + 4][lm] = bv1.x; Bs[lk + 5][lm] = bv1.y;
        Bs[lk + 6][lm] = bv1.z; Bs[lk + 7][lm] = bv1.w;
        __syncthreads();

        if (grpActive) {
#pragma unroll
            for (int kk = 0; kk < 16; ++kk) {
                const float4 a0 = *(const float4*)&As[kk][ty * 8];
                const float4 a1 = *(const float4*)&As[kk][ty * 8 + 4];
                const ulonglong2 bb0 = *(const ulonglong2*)&Bs[kk][tx * 8];
                const ulonglong2 bb1 = *(const ulonglong2*)&Bs[kk][tx * 8 + 4];
                const float a[8] = {a0.x, a0.y, a0.z, a0.w,
                                    a1.x, a1.y, a1.z, a1.w};
#pragma unroll
                for (int i = 0; i < 8; ++i) {
                    const unsigned long long ad = pack2(a[i], a[i]);
                    FMA2(acc2[i][0], ad, bb0.x);
                    FMA2(acc2[i][1], ad, bb0.y);
                    FMA2(acc2[i][2], ad, bb1.x);
                    FMA2(acc2[i][3], ad, bb1.y);
                }
            }
        }
        __syncthreads();
    }

    if (grpActive) {
#pragma unroll
        for (int i = 0; i < 8; ++i) {
            float f0, f1, f2, f3, f4, f5, f6, f7;
            unpack2(acc2[i][0], f0, f1);
            unpack2(acc2[i][1], f2, f3);
            unpack2(acc2[i][2], f4, f5);
            unpack2(acc2[i][3], f6, f7);
            const size_t o = ((size_t)t * Bsz + ty * 8 + i) * G4 + j0 + tx * 8;
            *(float4*)&g_G[o]     = make_float4(f0, f1, f2, f3);
            *(float4*)&g_G[o + 4] = make_float4(f4, f5, f6, f7);
        }
    }
}

// ---------------------------------------------------------------------------
// Per-btile software barrier (32 blocks), release/acquire atomics only.
// ---------------------------------------------------------------------------
__device__ __forceinline__ void tile_barrier(unsigned* cnt, unsigned* gen)
{
    __syncthreads();
    if (threadIdx.x == 0) {
        const unsigned old = ld_relaxed_gpu(gen);
        const unsigned ticket = atom_add_acqrel_gpu(cnt, 1u);
        if (ticket == 31u) {
            st_relaxed_gpu(cnt, 0u);
            st_release_gpu(gen, old + 1u);
        } else {
            while (ld_acquire_gpu(gen) == old) { }
        }
    }
    __syncthreads();
}

__device__ __forceinline__ float sigmf(float x) {
    return __fdividef(1.f, 1.f + __expf(-x));
}
__device__ __forceinline__ float tanh_fast(float x) {
    return 1.f - __fdividef(2.f, __expf(2.f * x) + 1.f);
}

// ---------------------------------------------------------------------------
// Phase 2: persistent recurrence, crossbar-minimal layout.
// 128 blocks = (btile 0..3 [32 rows]) x (ntile 0..31 [16 units]), 256 thr.
// smem (k-major): W_s[k][64]  c = nh*4+gate   (128 KB)
//                 h_s[k][32]                  (64 KB)
//                 P[2][32][PPITCH] gate partials per k-half (17 KB)
// GEMM decomposition: tid -> cg = tid&31 (col pair 2cg,2cg+1),
//   rg = (tid>>5)&3 (8-row group), kh = tid>>7 (k half of 256).
//   Acc lanes = (even row, odd row) pairs — natural from k-major LDS.128 of h.
//   Per k per warp: W 256B (2 wf) + h 2 broadcast LDS.128 (2 wf).
// Epilogue decomposition: tid -> r = tid&31, ug = tid>>5 (units 2ug, 2ug+1).
//   Reduces the two k-half partials, adds G, applies LSTM; c/h state lives in
//   the epilogue thread's registers across all 1024 steps.
// ---------------------------------------------------------------------------
__global__ void __launch_bounds__(256, 1) lstm_steps_kernel(
    const float* __restrict__ Whh,
    const int*   __restrict__ lensraw,
    float* __restrict__ out,    // [B,T,H]
    float* __restrict__ hfin,   // [B,H]
    float* __restrict__ cfin)   // [B,H]
{
    extern __shared__ float sm[];
    float* W_s = sm;                       // [512][64]
    float* h_s = sm + 512 * 64;            // [512][32]
    float* P_s = sm + 512 * 64 + 512 * 32; // [2][32][PPITCH]

    const int tid   = threadIdx.x;         // 0..255
    const int bx    = blockIdx.x;          // 0..127
    const int ntile = bx & 31;
    const int btile = bx >> 5;
    const int n0    = ntile * 16;
    const int b0    = btile * 32;
    unsigned* bar_cnt = &g_bar_cnt4[btile][0];
    unsigned* bar_gen = &g_bar_gen4[btile][0];

    // ---- stage W_hh (once): W_s[k][nh*4+gate] = Whh[gate*512 + n0+nh][k]
    {
        const int c     = tid >> 2;            // 0..63
        const int chunk = tid & 3;             // 128 k each
        const int gate  = c & 3;
        const int nh    = c >> 2;
        const float* wrow = Whh + (size_t)(gate * Hsz + n0 + nh) * Hsz;
        for (int k = chunk * 128; k < chunk * 128 + 128; k += 4) {
            const float4 v = *(const float4*)(wrow + k);
            W_s[(k + 0) * 64 + c] = v.x;
            W_s[(k + 1) * 64 + c] = v.y;
            W_s[(k + 2) * 64 + c] = v.z;
            W_s[(k + 3) * 64 + c] = v.w;
        }
    }
    // ---- zero this block's slice of hbuf[0]  (32 rows x 16 cols)
#pragma unroll
    for (int q = 0; q < 2; ++q) {
        const int idx = tid + q * 256;
        const int r = idx >> 4, cc = idx & 15;
        g_hbuf[0][(size_t)(b0 + r) * Hsz + n0 + cc] = 0.f;
    }
    // ---- zero-fill out for this btile: rows [b0,b0+32), t in [ntile*32,+32)
    {
        const float4 z4 = make_float4(0.f, 0.f, 0.f, 0.f);
        for (int it = 0; it < 512; ++it) {
            const int p  = it * 2 + (tid >> 7);
            const int r  = p >> 5;
            const int tt = ntile * 32 + (p & 31);
            float4* dst = (float4*)(out + ((size_t)(b0 + r) * Tsz + tt) * Hsz);
            dst[tid & 127] = z4;
        }
    }
    tile_barrier(bar_cnt, bar_gen);

    // ---- GEMM mapping
    const int cg = tid & 31;                 // col pair (2cg, 2cg+1)
    const int rg = (tid >> 5) & 3;           // 8-row group
    const int kh = tid >> 7;                 // k half
    const float* wbase = W_s + 2 * cg;
    const float* hbase = h_s + rg * 8;
    float* Pk = P_s + kh * (32 * PPITCH);

    // ---- epilogue mapping (same threads, different decomposition)
    const int er = tid & 31;                 // batch row local
    const int ug = tid >> 5;                 // unit group: units 2ug, 2ug+1
    const int eb = b0 + er;

    const bool is64 = lens_is64(lensraw);
    const int len_tile = load_len(lensraw, is64, b0);
    const int len_r    = load_len(lensraw, is64, eb);

    float hprev[2] = {0.f, 0.f};
    float creg [2] = {0.f, 0.f};

    // h staging mapping: b = tid&31, k chunk = tid>>5 (8 chunks of 64)
    const int st_b  = tid & 31;
    const int st_kc = tid >> 5;

#pragma unroll 1
    for (int t = 0; t < Tsz; ++t) {
        float* hnext = g_hbuf[(t + 1) & 1];
        const bool tileActive = (t < len_tile);

        if (tileActive) {
            // -- prefetch G[t] for epilogue (8 independent DRAM loads)
            const float* grb = g_G + ((size_t)t * Bsz + eb) * G4 + n0;
            float gpre[2][4];
#pragma unroll
            for (int u = 0; u < 2; ++u) {
                const int n = 2 * ug + u;
                gpre[u][0] = __ldcg(grb + n);
                gpre[u][1] = __ldcg(grb + 512 + n);
                gpre[u][2] = __ldcg(grb + 1024 + n);
                gpre[u][3] = __ldcg(grb + 1536 + n);
            }

            // -- stage h tile: h_s[k][b] (transposed, conflict-free STS)
            {
                const float* src = g_hbuf[t & 1] +
                                   (size_t)(b0 + st_b) * Hsz + st_kc * 64;
#pragma unroll
                for (int i = 0; i < 16; ++i) {
                    const float4 v = __ldcg((const float4*)(src + i * 4));
                    const int k = st_kc * 64 + i * 4;
                    h_s[(k + 0) * 32 + st_b] = v.x;
                    h_s[(k + 1) * 32 + st_b] = v.y;
                    h_s[(k + 2) * 32 + st_b] = v.z;
                    h_s[(k + 3) * 32 + st_b] = v.w;
                }
            }
            __syncthreads();

            // -- micro-GEMM over this thread's k half (8 rows x 2 cols)
            unsigned long long A00 = 0ull, A01 = 0ull;
            unsigned long long A10 = 0ull, A11 = 0ull;
            unsigned long long A20 = 0ull, A21 = 0ull;
            unsigned long long A30 = 0ull, A31 = 0ull;
            const int kend = kh * 256 + 256;
#pragma unroll 8
            for (int k = kh * 256; k < kend; ++k) {
                const float2 wv = *(const float2*)(wbase + k * 64);
                const ulonglong2 hA = *(const ulonglong2*)(hbase + k * 32);
                const ulonglong2 hB = *(const ulonglong2*)(hbase + k * 32 + 4);
                const unsigned long long w0 = pack2(wv.x, wv.x);
                const unsigned long long w1 = pack2(wv.y, wv.y);
                FMA2(A00, hA.x, w0); FMA2(A01, hA.x, w1);
                FMA2(A10, hA.y, w0); FMA2(A11, hA.y, w1);
                FMA2(A20, hB.x, w0); FMA2(A21, hB.x, w1);
                FMA2(A30, hB.y, w0); FMA2(A31, hB.y, w1);
            }
            // -- store partials (acc lanes = (even row, odd row))
            {
                float e0, o0, e1, o1;
                const int rb = rg * 8;
                unpack2(A00, e0, o0); unpack2(A01, e1, o1);
                Pk[(rb+0)*PPITCH + 2*cg] = e0; Pk[(rb+0)*PPITCH + 2*cg+1] = e1;
                Pk[(rb+1)*PPITCH + 2*cg] = o0; Pk[(rb+1)*PPITCH + 2*cg+1] = o1;
                unpack2(A10, e0, o0); unpack2(A11, e1, o1);
                Pk[(rb+2)*PPITCH + 2*cg] = e0; Pk[(rb+2)*PPITCH + 2*cg+1] = e1;
                Pk[(rb+3)*PPITCH + 2*cg] = o0; Pk[(rb+3)*PPITCH + 2*cg+1] = o1;
                unpack2(A20, e0, o0); unpack2(A21, e1, o1);
                Pk[(rb+4)*PPITCH + 2*cg] = e0; Pk[(rb+4)*PPITCH + 2*cg+1] = e1;
                Pk[(rb+5)*PPITCH + 2*cg] = o0; Pk[(rb+5)*PPITCH + 2*cg+1] = o1;
                unpack2(A30, e0, o0); unpack2(A31, e1, o1);
                Pk[(rb+6)*PPITCH + 2*cg] = e0; Pk[(rb+6)*PPITCH + 2*cg+1] = e1;
                Pk[(rb+7)*PPITCH + 2*cg] = o0; Pk[(rb+7)*PPITCH + 2*cg+1] = o1;
            }
            __syncthreads();

            // -- epilogue: reduce k-halves, add G, LSTM update (2 units)
#pragma unroll
            for (int u = 0; u < 2; ++u) {
                const int uu = 2 * ug + u;
                const float4 pa = *(const float4*)&P_s[er * PPITCH + uu * 4];
                const float4 pb = *(const float4*)&P_s[32 * PPITCH + er * PPITCH + uu * 4];
                const float ai = pa.x + pb.x;
                const float af = pa.y + pb.y;
                const float ag = pa.z + pb.z;
                const float ao = pa.w + pb.w;
                const float iv = sigmf(ai + gpre[u][0]);
                const float fv = sigmf(af + gpre[u][1]);
                const float gv = tanh_fast(ag + gpre[u][2]);
                const float ov = sigmf(ao + gpre[u][3]);
                const float cn = fv * creg[u] + iv * gv;
                const float hn = ov * tanh_fast(cn);
                const bool act = (t < len_r);
                creg [u] = act ? cn : creg[u];
                hprev[u] = act ? hn : hprev[u];
                if (act) out[((size_t)eb * Tsz + t) * Hsz + n0 + uu] = hn;
                hnext[(size_t)eb * Hsz + n0 + uu] = hprev[u];
            }
            __syncthreads();   // protect P_s/h_s reuse vs next step's staging
        }
        // inactive tile: outputs already zero-filled, h frozen

        tile_barrier(bar_cnt, bar_gen);   // h handoff within this btile
    }

    // final (frozen) states
#pragma unroll
    for (int u = 0; u < 2; ++u) {
        const int uu = 2 * ug + u;
        hfin[(size_t)eb * Hsz + n0 + uu] = hprev[u];
        cfin[(size_t)eb * Hsz + n0 + uu] = creg[u];
    }
}

// ---------------------------------------------------------------------------
extern "C" void kernel_launch(void* const* d_in, const int* in_sizes, int n_in,
                              void* d_out, int out_size)
{
    (void)in_sizes; (void)n_in; (void)out_size;
    const float* seq  = (const float*)d_in[0];
    const int*   lens = (const int*)d_in[1];
    const float* Wih  = (const float*)d_in[2];
    const float* Whh  = (const float*)d_in[3];
    const float* bih  = (const float*)d_in[4];
    const float* bhh  = (const float*)d_in[5];

    float* outp = (float*)d_out;
    float* hfin = outp + (size_t)Bsz * Tsz * Hsz;
    float* cfin = hfin + (size_t)Bsz * Hsz;

    // dynamic smem: W 128KB + h 64KB + partials 2*32*PPITCH*4 = 213,504+
    const int smem_bytes = (512 * 64 + 512 * 32 + 2 * 32 * PPITCH) * 4;
    cudaFuncSetAttribute(lstm_steps_kernel,
                         cudaFuncAttributeMaxDynamicSharedMemorySize, smem_bytes);

    // Phase 1: input-gate GEMM  (16 column tiles x 1024 timesteps)
    dim3 grid1(G4 / 128, Tsz);
    pregemm_kernel<<<grid1, 256>>>(seq, Wih, bih, bhh, lens);

    // Phase 2: persistent recurrence (128 co-resident blocks, btile barriers)
    lstm_steps_kernel<<<128, 256, smem_bytes>>>(Whh, lens, outp, hfin, cfin);
}

// round 11
// speedup vs baseline: 1.4538x; 1.0235x over previous
#include <cuda_runtime.h>
#include <math.h>

// ---------------------------------------------------------------------------
// Problem constants: B=128, T=1024, D=512, H=512, 4H=2048
//   0: sequence_tensor f32 [128,1024,512]
//   1: batch_lengths   int32 (JAX x64 off) or int64 [128], sorted descending
//   2: W_ih f32 [2048,512]   3: W_hh f32 [2048,512]
//   4: b_ih f32 [2048]       5: b_hh f32 [2048]
// Output: concat( out[128,1024,512], h_final[1,128,512], c_final[1,128,512] )
// ---------------------------------------------------------------------------

#define Bsz   128
#define Tsz   1024
#define Dsz   512
#define Hsz   512
#define G4    2048
#define PPITCH 68   // gate-partial smem row pitch (floats): conflict-free LDS.128

// Scratch: precomputed input gates  G[t][b][j]  (1 GiB)
__device__ float g_G[(size_t)Tsz * Bsz * G4];
// Double-buffered hidden state h[b][k]
__device__ float g_hbuf[2][Bsz * Hsz];
// Per-btile barrier state (4 btiles, 128B-padded lines)
__device__ __align__(128) unsigned g_bar_cnt4[4][32];
__device__ __align__(128) unsigned g_bar_gen4[4][32];

// ---- packed fp32 helpers (FFMA2 path: PTX fma.rn.f32x2) --------------------
__device__ __forceinline__ unsigned long long pack2(float x, float y) {
    unsigned long long r;
    asm("mov.b64 %0, {%1, %2};" : "=l"(r) : "f"(x), "f"(y));
    return r;
}
__device__ __forceinline__ void unpack2(unsigned long long v, float& x, float& y) {
    asm("mov.b64 {%0, %1}, %2;" : "=f"(x), "=f"(y) : "l"(v));
}
#define FMA2(d, a, b) asm("fma.rn.f32x2 %0, %1, %2, %0;" : "+l"(d) : "l"(a), "l"(b))

// ---- scoped atomics for the software barrier --------------------------------
__device__ __forceinline__ unsigned ld_acquire_gpu(unsigned* p) {
    unsigned v;
    asm volatile("ld.acquire.gpu.u32 %0, [%1];" : "=r"(v) : "l"(p) : "memory");
    return v;
}
__device__ __forceinline__ unsigned ld_relaxed_gpu(unsigned* p) {
    unsigned v;
    asm volatile("ld.relaxed.gpu.u32 %0, [%1];" : "=r"(v) : "l"(p) : "memory");
    return v;
}
__device__ __forceinline__ unsigned atom_add_acqrel_gpu(unsigned* p, unsigned v) {
    unsigned o;
    asm volatile("atom.add.acq_rel.gpu.u32 %0, [%1], %2;"
                 : "=r"(o) : "l"(p), "r"(v) : "memory");
    return o;
}
__device__ __forceinline__ void st_release_gpu(unsigned* p, unsigned v) {
    asm volatile("st.release.gpu.u32 [%0], %1;" :: "l"(p), "r"(v) : "memory");
}
__device__ __forceinline__ void st_relaxed_gpu(unsigned* p, unsigned v) {
    asm volatile("st.relaxed.gpu.u32 [%0], %1;" :: "l"(p), "r"(v) : "memory");
}

// ---- length dtype detection (int32 vs int64) --------------------------------
__device__ __forceinline__ bool lens_is64(const int* p) {
    return (p[1] == 0 && p[3] == 0 && p[5] == 0);
}
__device__ __forceinline__ int load_len(const int* p, bool is64, int b) {
    return is64 ? p[2 * b] : p[b];
}

// ---------------------------------------------------------------------------
// Phase 1: G[t][b][j] = sum_k seq[b][t][k] * W_ih[j][k] + (b_ih[j] + b_hh[j])
// 128x128x16 SGEMM per block, FFMA2.  ~93% of FFMA2 pipe floor — unchanged.
// ---------------------------------------------------------------------------
__global__ void __launch_bounds__(256) pregemm_kernel(
    const float* __restrict__ seq,
    const float* __restrict__ Wih,
    const float* __restrict__ bih,
    const float* __restrict__ bhh,
    const int*   __restrict__ lensraw)
{
    __shared__ float As[16][128];
    __shared__ float Bs[16][128];

    const int t   = blockIdx.y;
    const int j0  = blockIdx.x * 128;
    const int tid = threadIdx.x;
    const int tx  = tid & 15;
    const int ty  = tid >> 4;

    const bool is64 = lens_is64(lensraw);
    const bool grpActive = (load_len(lensraw, is64, ty * 8) > t);

    unsigned long long acc2[8][4];
#pragma unroll
    for (int p = 0; p < 4; ++p) {
        const int j = j0 + tx * 8 + 2 * p;
        const unsigned long long bv =
            pack2(bih[j] + bhh[j], bih[j + 1] + bhh[j + 1]);
#pragma unroll
        for (int i = 0; i < 8; ++i) acc2[i][p] = bv;
    }

    const int lm = tid >> 1;
    const int lk = (tid & 1) * 8;
    const float* arow = seq + ((size_t)lm * Tsz + t) * Dsz + lk;
    const float* brow = Wih + (size_t)(j0 + lm) * Dsz + lk;

    for (int k0 = 0; k0 < Dsz; k0 += 16) {
        const float4 av0 = *(const float4*)(arow + k0);
        const float4 av1 = *(const float4*)(arow + k0 + 4);
        const float4 bv0 = *(const float4*)(brow + k0);
        const float4 bv1 = *(const float4*)(brow + k0 + 4);
        As[lk + 0][lm] = av0.x; As[lk + 1][lm] = av0.y;
        As[lk + 2][lm] = av0.z; As[lk + 3][lm] = av0.w;
        As[lk + 4][lm] = av1.x; As[lk + 5][lm] = av1.y;
        As[lk + 6][lm] = av1.z; As[lk + 7][lm] = av1.w;
        Bs[lk + 0][lm] = bv0.x; Bs[lk + 1][lm] = bv0.y;
        Bs[lk + 2][lm] = bv0.z; Bs[lk + 3][lm] = bv0.w;
        Bs[lk + 4][lm] = bv1.x; Bs[lk + 5][lm] = bv1.y;
        Bs[lk + 6][lm] = bv1.z; Bs[lk + 7][lm] = bv1.w;
        __syncthreads();

        if (grpActive) {
#pragma unroll
            for (int kk = 0; kk < 16; ++kk) {
                const float4 a0 = *(const float4*)&As[kk][ty * 8];
                const float4 a1 = *(const float4*)&As[kk][ty * 8 + 4];
                const ulonglong2 bb0 = *(const ulonglong2*)&Bs[kk][tx * 8];
                const ulonglong2 bb1 = *(const ulonglong2*)&Bs[kk][tx * 8 + 4];
                const float a[8] = {a0.x, a0.y, a0.z, a0.w,
                                    a1.x, a1.y, a1.z, a1.w};
#pragma unroll
                for (int i = 0; i < 8; ++i) {
                    const unsigned long long ad = pack2(a[i], a[i]);
                    FMA2(acc2[i][0], ad, bb0.x);
                    FMA2(acc2[i][1], ad, bb0.y);
                    FMA2(acc2[i][2], ad, bb1.x);
                    FMA2(acc2[i][3], ad, bb1.y);
                }
            }
        }
        __syncthreads();
    }

    if (grpActive) {
#pragma unroll
        for (int i = 0; i < 8; ++i) {
            float f0, f1, f2, f3, f4, f5, f6, f7;
            unpack2(acc2[i][0], f0, f1);
            unpack2(acc2[i][1], f2, f3);
            unpack2(acc2[i][2], f4, f5);
            unpack2(acc2[i][3], f6, f7);
            const size_t o = ((size_t)t * Bsz + ty * 8 + i) * G4 + j0 + tx * 8;
            *(float4*)&g_G[o]     = make_float4(f0, f1, f2, f3);
            *(float4*)&g_G[o + 4] = make_float4(f4, f5, f6, f7);
        }
    }
}

// ---------------------------------------------------------------------------
// Per-btile software barrier (32 blocks), release/acquire atomics only.
// ---------------------------------------------------------------------------
__device__ __forceinline__ void tile_barrier(unsigned* cnt, unsigned* gen)
{
    __syncthreads();
    if (threadIdx.x == 0) {
        const unsigned old = ld_relaxed_gpu(gen);
        const unsigned ticket = atom_add_acqrel_gpu(cnt, 1u);
        if (ticket == 31u) {
            st_relaxed_gpu(cnt, 0u);
            st_release_gpu(gen, old + 1u);
        } else {
            while (ld_acquire_gpu(gen) == old) { }
        }
    }
    __syncthreads();
}

__device__ __forceinline__ float sigmf(float x) {
    return __fdividef(1.f, 1.f + __expf(-x));
}
__device__ __forceinline__ float tanh_fast(float x) {
    return 1.f - __fdividef(2.f, __expf(2.f * x) + 1.f);
}

// ---------------------------------------------------------------------------
// Phase 2: persistent recurrence, crossbar-minimal layout, 512 threads.
// 128 blocks = (btile 0..3 [32 rows]) x (ntile 0..31 [16 units]).
// smem (k-major): W_s[k][64]  c = nh*4+gate   (128 KB)
//                 h_s[k][32]                  (64 KB)
//                 P[4][32][PPITCH] gate partials per k-quarter (34 KB)
// GEMM: tid -> cg = tid&31 (col pair), rg = (tid>>5)&3 (8-row group),
//       kq = tid>>7 (k quarter of 128).  16 warps -> 4 warps/SMSP.
//       Acc lanes = (even row, odd row) pairs from k-major LDS.128 of h.
//       Per k per warp: W 256B (2 wf) + h 2 broadcast LDS.128 (2 wf).
// Epilogue: tid -> er = tid&31 (row), un = tid>>5 (unit 0..15); exactly one
//       LSTM cell per thread; c/h state in registers across all steps.
// ---------------------------------------------------------------------------
__global__ void __launch_bounds__(512, 1) lstm_steps_kernel(
    const float* __restrict__ Whh,
    const int*   __restrict__ lensraw,
    float* __restrict__ out,    // [B,T,H]
    float* __restrict__ hfin,   // [B,H]
    float* __restrict__ cfin)   // [B,H]
{
    extern __shared__ float sm[];
    float* W_s = sm;                       // [512][64]
    float* h_s = sm + 512 * 64;            // [512][32]
    float* P_s = sm + 512 * 64 + 512 * 32; // [4][32][PPITCH]

    const int tid   = threadIdx.x;         // 0..511
    const int bx    = blockIdx.x;          // 0..127
    const int ntile = bx & 31;
    const int btile = bx >> 5;
    const int n0    = ntile * 16;
    const int b0    = btile * 32;
    unsigned* bar_cnt = &g_bar_cnt4[btile][0];
    unsigned* bar_gen = &g_bar_gen4[btile][0];

    // ---- stage W_hh (once): W_s[k][nh*4+gate] = Whh[gate*512 + n0+nh][k]
    {
        const int c     = tid >> 3;            // 0..63
        const int chunk = tid & 7;             // 64 k each
        const int gate  = c & 3;
        const int nh    = c >> 2;
        const float* wrow = Whh + (size_t)(gate * Hsz + n0 + nh) * Hsz;
        for (int k = chunk * 64; k < chunk * 64 + 64; k += 4) {
            const float4 v = *(const float4*)(wrow + k);
            W_s[(k + 0) * 64 + c] = v.x;
            W_s[(k + 1) * 64 + c] = v.y;
            W_s[(k + 2) * 64 + c] = v.z;
            W_s[(k + 3) * 64 + c] = v.w;
        }
    }
    // ---- zero this block's slice of hbuf[0]  (32 rows x 16 cols = 512)
    {
        const int r = tid >> 4, cc = tid & 15;
        g_hbuf[0][(size_t)(b0 + r) * Hsz + n0 + cc] = 0.f;
    }
    // ---- zero-fill out for this btile: rows [b0,b0+32), t in [ntile*32,+32)
    {
        const float4 z4 = make_float4(0.f, 0.f, 0.f, 0.f);
        for (int it = 0; it < 256; ++it) {
            const int idx = it * 512 + tid;       // float4 index 0..131071
            const int bt  = idx >> 7;             // (b,t) pair 0..1023
            const int f4  = idx & 127;
            const int r   = bt >> 5;
            const int tt  = ntile * 32 + (bt & 31);
            float4* dst = (float4*)(out + ((size_t)(b0 + r) * Tsz + tt) * Hsz);
            dst[f4] = z4;
        }
    }
    tile_barrier(bar_cnt, bar_gen);

    // ---- GEMM mapping
    const int cg = tid & 31;                 // col pair (2cg, 2cg+1)
    const int rg = (tid >> 5) & 3;           // 8-row group
    const int kq = tid >> 7;                 // k quarter (0..3)
    const float* wbase = W_s + 2 * cg;
    const float* hbase = h_s + rg * 8;
    float* Pk = P_s + kq * (32 * PPITCH);

    // ---- epilogue mapping: one (row, unit) per thread
    const int er = tid & 31;                 // batch row local
    const int un = tid >> 5;                 // hidden unit local 0..15
    const int eb = b0 + er;
    const int n  = n0 + un;

    const bool is64 = lens_is64(lensraw);
    const int len_tile = load_len(lensraw, is64, b0);
    const int len_r    = load_len(lensraw, is64, eb);

    float hprev = 0.f, creg = 0.f;

    // h staging mapping: b = tid&31, k chunk = tid>>5 (16 chunks of 32)
    const int st_b  = tid & 31;
    const int st_kc = tid >> 5;

#pragma unroll 1
    for (int t = 0; t < Tsz; ++t) {
        float* hnext = g_hbuf[(t + 1) & 1];
        const bool tileActive = (t < len_tile);

        if (tileActive) {
            // -- prefetch G[t] for epilogue (4 independent DRAM loads)
            const float* grb = g_G + ((size_t)t * Bsz + eb) * G4 + n;
            const float gi = __ldcg(grb);
            const float gf = __ldcg(grb + 512);
            const float gg = __ldcg(grb + 1024);
            const float go = __ldcg(grb + 1536);

            // -- stage h tile: h_s[k][b] (transposed, conflict-free STS)
            {
                const float* src = g_hbuf[t & 1] +
                                   (size_t)(b0 + st_b) * Hsz + st_kc * 32;
#pragma unroll
                for (int i = 0; i < 8; ++i) {
                    const float4 v = __ldcg((const float4*)(src + i * 4));
                    const int k = st_kc * 32 + i * 4;
                    h_s[(k + 0) * 32 + st_b] = v.x;
                    h_s[(k + 1) * 32 + st_b] = v.y;
                    h_s[(k + 2) * 32 + st_b] = v.z;
                    h_s[(k + 3) * 32 + st_b] = v.w;
                }
            }
            __syncthreads();

            // -- micro-GEMM over this thread's k quarter (8 rows x 2 cols)
            unsigned long long A00 = 0ull, A01 = 0ull;
            unsigned long long A10 = 0ull, A11 = 0ull;
            unsigned long long A20 = 0ull, A21 = 0ull;
            unsigned long long A30 = 0ull, A31 = 0ull;
            const int kend = kq * 128 + 128;
#pragma unroll 8
            for (int k = kq * 128; k < kend; ++k) {
                const float2 wv = *(const float2*)(wbase + k * 64);
                const ulonglong2 hA = *(const ulonglong2*)(hbase + k * 32);
                const ulonglong2 hB = *(const ulonglong2*)(hbase + k * 32 + 4);
                const unsigned long long w0 = pack2(wv.x, wv.x);
                const unsigned long long w1 = pack2(wv.y, wv.y);
                FMA2(A00, hA.x, w0); FMA2(A01, hA.x, w1);
                FMA2(A10, hA.y, w0); FMA2(A11, hA.y, w1);
                FMA2(A20, hB.x, w0); FMA2(A21, hB.x, w1);
                FMA2(A30, hB.y, w0); FMA2(A31, hB.y, w1);
            }
            // -- store partials: float2 per row = (col 2cg, col 2cg+1)
            {
                float e0, o0, e1, o1;
                const int rb = rg * 8;
                float2* pr;
                unpack2(A00, e0, o0); unpack2(A01, e1, o1);
                pr = (float2*)&Pk[(rb+0)*PPITCH + 2*cg]; *pr = make_float2(e0, e1);
                pr = (float2*)&Pk[(rb+1)*PPITCH + 2*cg]; *pr = make_float2(o0, o1);
                unpack2(A10, e0, o0); unpack2(A11, e1, o1);
                pr = (float2*)&Pk[(rb+2)*PPITCH + 2*cg]; *pr = make_float2(e0, e1);
                pr = (float2*)&Pk[(rb+3)*PPITCH + 2*cg]; *pr = make_float2(o0, o1);
                unpack2(A20, e0, o0); unpack2(A21, e1, o1);
                pr = (float2*)&Pk[(rb+4)*PPITCH + 2*cg]; *pr = make_float2(e0, e1);
                pr = (float2*)&Pk[(rb+5)*PPITCH + 2*cg]; *pr = make_float2(o0, o1);
                unpack2(A30, e0, o0); unpack2(A31, e1, o1);
                pr = (float2*)&Pk[(rb+6)*PPITCH + 2*cg]; *pr = make_float2(e0, e1);
                pr = (float2*)&Pk[(rb+7)*PPITCH + 2*cg]; *pr = make_float2(o0, o1);
            }
            __syncthreads();

            // -- epilogue: reduce 4 k-quarters, add G, LSTM update (1 cell)
            {
                const float4 p0 = *(const float4*)&P_s[0*32*PPITCH + er*PPITCH + un*4];
                const float4 p1 = *(const float4*)&P_s[1*32*PPITCH + er*PPITCH + un*4];
                const float4 p2 = *(const float4*)&P_s[2*32*PPITCH + er*PPITCH + un*4];
                const float4 p3 = *(const float4*)&P_s[3*32*PPITCH + er*PPITCH + un*4];
                const float ai = (p0.x + p1.x) + (p2.x + p3.x);
                const float af = (p0.y + p1.y) + (p2.y + p3.y);
                const float ag = (p0.z + p1.z) + (p2.z + p3.z);
                const float ao = (p0.w + p1.w) + (p2.w + p3.w);
                const float iv = sigmf(ai + gi);
                const float fv = sigmf(af + gf);
                const float gv = tanh_fast(ag + gg);
                const float ov = sigmf(ao + go);
                const float cn = fv * creg + iv * gv;
                const float hn = ov * tanh_fast(cn);
                const bool act = (t < len_r);
                creg  = act ? cn : creg;
                hprev = act ? hn : hprev;
                if (act) out[((size_t)eb * Tsz + t) * Hsz + n] = hn;
                hnext[(size_t)eb * Hsz + n] = hprev;
            }
            // (tile_barrier's entry __syncthreads protects P_s/h_s reuse)
        }
        // inactive tile: outputs already zero-filled, h frozen

        tile_barrier(bar_cnt, bar_gen);   // h handoff within this btile
    }

    // final (frozen) states
    hfin[(size_t)eb * Hsz + n] = hprev;
    cfin[(size_t)eb * Hsz + n] = creg;
}

// ---------------------------------------------------------------------------
extern "C" void kernel_launch(void* const* d_in, const int* in_sizes, int n_in,
                              void* d_out, int out_size)
{
    (void)in_sizes; (void)n_in; (void)out_size;
    const float* seq  = (const float*)d_in[0];
    const int*   lens = (const int*)d_in[1];
    const float* Wih  = (const float*)d_in[2];
    const float* Whh  = (const float*)d_in[3];
    const float* bih  = (const float*)d_in[4];
    const float* bhh  = (const float*)d_in[5];

    float* outp = (float*)d_out;
    float* hfin = outp + (size_t)Bsz * Tsz * Hsz;
    float* cfin = hfin + (size_t)Bsz * Hsz;

    // dynamic smem: W 128KB + h 64KB + partials 4*32*PPITCH*4 = 231,424 B
    const int smem_bytes = (512 * 64 + 512 * 32 + 4 * 32 * PPITCH) * 4;
    cudaFuncSetAttribute(lstm_steps_kernel,
                         cudaFuncAttributeMaxDynamicSharedMemorySize, smem_bytes);

    // Phase 1: input-gate GEMM  (16 column tiles x 1024 timesteps)
    dim3 grid1(G4 / 128, Tsz);
    pregemm_kernel<<<grid1, 256>>>(seq, Wih, bih, bhh, lens);

    // Phase 2: persistent recurrence (128 co-resident blocks, btile barriers)
    lstm_steps_kernel<<<128, 512, smem_bytes>>>(Whh, lens, outp, hfin, cfin);
}

// round 14
// speedup vs baseline: 1.5113x; 1.0396x over previous
#include <cuda_runtime.h>
#include <cstdint>
#include <math.h>

// ---------------------------------------------------------------------------
// Problem constants: B=128, T=1024, D=512, H=512, 4H=2048
//   0: sequence_tensor f32 [128,1024,512]
//   1: batch_lengths   int32 (JAX x64 off) or int64 [128], sorted descending
//   2: W_ih f32 [2048,512]   3: W_hh f32 [2048,512]
//   4: b_ih f32 [2048]       5: b_hh f32 [2048]
// Output: concat( out[128,1024,512], h_final[1,128,512], c_final[1,128,512] )
//
// NOTE: harness lowers PTX through compute_103 (non-'a') -> tcgen05 is
// UNAVAILABLE here (ptxas rejects it).  FFMA2 roofline is the ceiling.
// ---------------------------------------------------------------------------

#define Bsz   128
#define Tsz   1024
#define Dsz   512
#define Hsz   512
#define G4    2048
#define PPITCH 68

// G stored TRANSPOSED: G[t][j][b]  (j = gate col 0..2047, b = batch row).
// Both the phase-1 epilogue stores and the phase-2 gate prefetch are then
// warp-coalesced (the old [t][b][j] prefetch was a 32-sector scatter).
__device__ float g_G[(size_t)Tsz * G4 * Bsz];
__device__ float g_hbuf[2][Bsz * Hsz];
__device__ __align__(128) unsigned g_bar_cnt4[4][32];
__device__ __align__(128) unsigned g_bar_gen4[4][32];

// ---- packed fp32 helpers (FFMA2 via PTX fma.rn.f32x2) -----------------------
__device__ __forceinline__ unsigned long long pack2(float x, float y) {
    unsigned long long r;
    asm("mov.b64 %0, {%1, %2};" : "=l"(r) : "f"(x), "f"(y));
    return r;
}
__device__ __forceinline__ void unpack2(unsigned long long v, float& x, float& y) {
    asm("mov.b64 {%0, %1}, %2;" : "=f"(x), "=f"(y) : "l"(v));
}
#define FMA2(d, a, b) asm("fma.rn.f32x2 %0, %1, %2, %0;" : "+l"(d) : "l"(a), "l"(b))

// ---- scoped atomics for the software barrier --------------------------------
__device__ __forceinline__ unsigned ld_acquire_gpu(unsigned* p) {
    unsigned v;
    asm volatile("ld.acquire.gpu.u32 %0, [%1];" : "=r"(v) : "l"(p) : "memory");
    return v;
}
__device__ __forceinline__ unsigned ld_relaxed_gpu(unsigned* p) {
    unsigned v;
    asm volatile("ld.relaxed.gpu.u32 %0, [%1];" : "=r"(v) : "l"(p) : "memory");
    return v;
}
__device__ __forceinline__ unsigned atom_add_acqrel_gpu(unsigned* p, unsigned v) {
    unsigned o;
    asm volatile("atom.add.acq_rel.gpu.u32 %0, [%1], %2;"
                 : "=r"(o) : "l"(p), "r"(v) : "memory");
    return o;
}
__device__ __forceinline__ void st_release_gpu(unsigned* p, unsigned v) {
    asm volatile("st.release.gpu.u32 [%0], %1;" :: "l"(p), "r"(v) : "memory");
}
__device__ __forceinline__ void st_relaxed_gpu(unsigned* p, unsigned v) {
    asm volatile("st.relaxed.gpu.u32 [%0], %1;" :: "l"(p), "r"(v) : "memory");
}

// ---- length dtype detection --------------------------------------------------
__device__ __forceinline__ bool lens_is64(const int* p) {
    return (p[1] == 0 && p[3] == 0 && p[5] == 0);
}
__device__ __forceinline__ int load_len(const int* p, bool is64, int b) {
    return is64 ? p[2 * b] : p[b];
}

// ---------------------------------------------------------------------------
// Phase 1: G[t][j][b] = sum_k W_ih[j][k] * seq[b][t][k] + (b_ih[j] + b_hh[j])
// 128x128x16 SGEMM per block, FFMA2.  A/B roles SWAPPED vs earlier rounds so
// the output tile has rows = gates (j) and cols = batch (b): epilogue float4
// stores are contiguous in b, matching the transposed G layout.
//   As = W_ih rows (gates), Bs = seq rows (batch).
//   acc rows i -> gate j0 + ty*8 + i   (bias per row)
//   acc cols  -> batch  tx*8 + ...     (length mask per tx group)
// ---------------------------------------------------------------------------
__global__ void __launch_bounds__(256) pregemm_kernel(
    const float* __restrict__ seq,
    const float* __restrict__ Wih,
    const float* __restrict__ bih,
    const float* __restrict__ bhh,
    const int*   __restrict__ lensraw)
{
    __shared__ float As[16][128];
    __shared__ float Bs[16][128];

    const int t   = blockIdx.y;
    const int j0  = blockIdx.x * 128;
    const int tid = threadIdx.x;
    const int tx  = tid & 15;            // batch col group (8 rows of b)
    const int ty  = tid >> 4;            // gate row group

    const bool is64 = lens_is64(lensraw);
    // cols tx*8 .. tx*8+7 are batch rows; lens sorted desc
    const bool grpActive = (load_len(lensraw, is64, tx * 8) > t);

    // acc2[i][p]: packed batch pair (b = tx*8 + 2p, +1) for gate row i
    unsigned long long acc2[8][4];
#pragma unroll
    for (int i = 0; i < 8; ++i) {
        const int j = j0 + ty * 8 + i;
        const float bv = bih[j] + bhh[j];
        const unsigned long long bb = pack2(bv, bv);
#pragma unroll
        for (int p = 0; p < 4; ++p) acc2[i][p] = bb;
    }

    const int lm = tid >> 1;
    const int lk = (tid & 1) * 8;
    const float* arow = Wih + (size_t)(j0 + lm) * Dsz + lk;          // gates
    const float* brow = seq + ((size_t)lm * Tsz + t) * Dsz + lk;     // batch

    for (int k0 = 0; k0 < Dsz; k0 += 16) {
        const float4 av0 = *(const float4*)(arow + k0);
        const float4 av1 = *(const float4*)(arow + k0 + 4);
        const float4 bv0 = *(const float4*)(brow + k0);
        const float4 bv1 = *(const float4*)(brow + k0 + 4);
        As[lk + 0][lm] = av0.x; As[lk + 1][lm] = av0.y;
        As[lk + 2][lm] = av0.z; As[lk + 3][lm] = av0.w;
        As[lk + 4][lm] = av1.x; As[lk + 5][lm] = av1.y;
        As[lk + 6][lm] = av1.z; As[lk + 7][lm] = av1.w;
        Bs[lk + 0][lm] = bv0.x; Bs[lk + 1][lm] = bv0.y;
        Bs[lk + 2][lm] = bv0.z; Bs[lk + 3][lm] = bv0.w;
        Bs[lk + 4][lm] = bv1.x; Bs[lk + 5][lm] = bv1.y;
        Bs[lk + 6][lm] = bv1.z; Bs[lk + 7][lm] = bv1.w;
        __syncthreads();

        if (grpActive) {
#pragma unroll
            for (int kk = 0; kk < 16; ++kk) {
                const float4 a0 = *(const float4*)&As[kk][ty * 8];
                const float4 a1 = *(const float4*)&As[kk][ty * 8 + 4];
                const ulonglong2 bb0 = *(const ulonglong2*)&Bs[kk][tx * 8];
                const ulonglong2 bb1 = *(const ulonglong2*)&Bs[kk][tx * 8 + 4];
                const float a[8] = {a0.x, a0.y, a0.z, a0.w,
                                    a1.x, a1.y, a1.z, a1.w};
#pragma unroll
                for (int i = 0; i < 8; ++i) {
                    const unsigned long long ad = pack2(a[i], a[i]);
                    FMA2(acc2[i][0], ad, bb0.x);
                    FMA2(acc2[i][1], ad, bb0.y);
                    FMA2(acc2[i][2], ad, bb1.x);
                    FMA2(acc2[i][3], ad, bb1.y);
                }
            }
        }
        __syncthreads();
    }

    if (grpActive) {
        float* Gt = g_G + ((size_t)t << 18);     // 2048*128 = 1<<18
#pragma unroll
        for (int i = 0; i < 8; ++i) {
            float f0, f1, f2, f3, f4, f5, f6, f7;
            unpack2(acc2[i][0], f0, f1);
            unpack2(acc2[i][1], f2, f3);
            unpack2(acc2[i][2], f4, f5);
            unpack2(acc2[i][3], f6, f7);
            const size_t o = (size_t)(j0 + ty * 8 + i) * Bsz + tx * 8;
            *(float4*)&Gt[o]     = make_float4(f0, f1, f2, f3);
            *(float4*)&Gt[o + 4] = make_float4(f4, f5, f6, f7);
        }
    }
}

// =============================================================================
// Per-btile software barrier (32 blocks), release/acquire atomics only.
// =============================================================================
__device__ __forceinline__ void tile_barrier(unsigned* cnt, unsigned* gen)
{
    __syncthreads();
    if (threadIdx.x == 0) {
        const unsigned old = ld_relaxed_gpu(gen);
        const unsigned ticket = atom_add_acqrel_gpu(cnt, 1u);
        if (ticket == 31u) {
            st_relaxed_gpu(cnt, 0u);
            st_release_gpu(gen, old + 1u);
        } else {
            while (ld_acquire_gpu(gen) == old) { }
        }
    }
    __syncthreads();
}

__device__ __forceinline__ float sigmf(float x) {
    return __fdividef(1.f, 1.f + __expf(-x));
}
__device__ __forceinline__ float tanh_fast(float x) {
    return 1.f - __fdividef(2.f, __expf(2.f * x) + 1.f);
}

// =============================================================================
// Phase 2: persistent recurrence (round-11 structure; G now [t][j][b]).
// 128 blocks = (btile 0..3 [32 rows]) x (ntile 0..31 [16 units]), 512 thr.
// =============================================================================
__global__ void __launch_bounds__(512, 1) lstm_steps_kernel(
    const float* __restrict__ Whh,
    const int*   __restrict__ lensraw,
    float* __restrict__ out,    // [B,T,H]
    float* __restrict__ hfin,   // [B,H]
    float* __restrict__ cfin)   // [B,H]
{
    extern __shared__ float sm[];
    float* W_s = sm;                       // [512][64]
    float* h_s = sm + 512 * 64;            // [512][32]
    float* P_s = sm + 512 * 64 + 512 * 32; // [4][32][PPITCH]

    const int tid   = threadIdx.x;
    const int bx    = blockIdx.x;
    const int ntile = bx & 31;
    const int btile = bx >> 5;
    const int n0    = ntile * 16;
    const int b0    = btile * 32;
    unsigned* bar_cnt = &g_bar_cnt4[btile][0];
    unsigned* bar_gen = &g_bar_gen4[btile][0];

    // ---- stage W_hh (once): W_s[k][nh*4+gate] = Whh[gate*512 + n0+nh][k]
    {
        const int c     = tid >> 3;
        const int chunk = tid & 7;
        const int gate  = c & 3;
        const int nh    = c >> 2;
        const float* wrow = Whh + (size_t)(gate * Hsz + n0 + nh) * Hsz;
        for (int k = chunk * 64; k < chunk * 64 + 64; k += 4) {
            const float4 v = *(const float4*)(wrow + k);
            W_s[(k + 0) * 64 + c] = v.x;
            W_s[(k + 1) * 64 + c] = v.y;
            W_s[(k + 2) * 64 + c] = v.z;
            W_s[(k + 3) * 64 + c] = v.w;
        }
    }
    // ---- zero this block's slice of hbuf[0]
    {
        const int r = tid >> 4, cc = tid & 15;
        g_hbuf[0][(size_t)(b0 + r) * Hsz + n0 + cc] = 0.f;
    }
    // ---- zero-fill out for this btile
    {
        const float4 z4 = make_float4(0.f, 0.f, 0.f, 0.f);
        for (int it = 0; it < 256; ++it) {
            const int idx = it * 512 + tid;
            const int bt  = idx >> 7;
            const int f4  = idx & 127;
            const int r   = bt >> 5;
            const int tt  = ntile * 32 + (bt & 31);
            float4* dst = (float4*)(out + ((size_t)(b0 + r) * Tsz + tt) * Hsz);
            dst[f4] = z4;
        }
    }
    tile_barrier(bar_cnt, bar_gen);

    // ---- GEMM mapping
    const int cg = tid & 31;
    const int rg = (tid >> 5) & 3;
    const int kq = tid >> 7;
    const float* wbase = W_s + 2 * cg;
    const float* hbase = h_s + rg * 8;
    float* Pk = P_s + kq * (32 * PPITCH);

    // ---- epilogue mapping: one (row, unit) per thread
    const int er = tid & 31;
    const int un = tid >> 5;
    const int eb = b0 + er;
    const int n  = n0 + un;

    const bool is64 = lens_is64(lensraw);
    const int len_tile = load_len(lensraw, is64, b0);
    const int len_r    = load_len(lensraw, is64, eb);

    float hprev = 0.f, creg = 0.f;

    const int st_b  = tid & 31;
    const int st_kc = tid >> 5;

#pragma unroll 1
    for (int t = 0; t < Tsz; ++t) {
        float* hnext = g_hbuf[(t + 1) & 1];
        const bool tileActive = (t < len_tile);

        if (tileActive) {
            // -- prefetch G[t] (coalesced: lanes = consecutive b)
            const float* grb = g_G + ((size_t)t << 18) + (size_t)n * Bsz + eb;
            const float gi = __ldcg(grb);
            const float gf = __ldcg(grb + 512 * Bsz);
            const float gg = __ldcg(grb + 1024 * Bsz);
            const float go = __ldcg(grb + 1536 * Bsz);

            // -- stage h tile: h_s[k][b]
            {
                const float* src = g_hbuf[t & 1] +
                                   (size_t)(b0 + st_b) * Hsz + st_kc * 32;
#pragma unroll
                for (int i = 0; i < 8; ++i) {
                    const float4 v = __ldcg((const float4*)(src + i * 4));
                    const int k = st_kc * 32 + i * 4;
                    h_s[(k + 0) * 32 + st_b] = v.x;
                    h_s[(k + 1) * 32 + st_b] = v.y;
                    h_s[(k + 2) * 32 + st_b] = v.z;
                    h_s[(k + 3) * 32 + st_b] = v.w;
                }
            }
            __syncthreads();

            // -- micro-GEMM over this thread's k quarter (8 rows x 2 cols)
            unsigned long long A00 = 0ull, A01 = 0ull;
            unsigned long long A10 = 0ull, A11 = 0ull;
            unsigned long long A20 = 0ull, A21 = 0ull;
            unsigned long long A30 = 0ull, A31 = 0ull;
            const int kend = kq * 128 + 128;
#pragma unroll 8
            for (int k = kq * 128; k < kend; ++k) {
                const float2 wv = *(const float2*)(wbase + k * 64);
                const ulonglong2 hA = *(const ulonglong2*)(hbase + k * 32);
                const ulonglong2 hB = *(const ulonglong2*)(hbase + k * 32 + 4);
                const unsigned long long w0 = pack2(wv.x, wv.x);
                const unsigned long long w1 = pack2(wv.y, wv.y);
                FMA2(A00, hA.x, w0); FMA2(A01, hA.x, w1);
                FMA2(A10, hA.y, w0); FMA2(A11, hA.y, w1);
                FMA2(A20, hB.x, w0); FMA2(A21, hB.x, w1);
                FMA2(A30, hB.y, w0); FMA2(A31, hB.y, w1);
            }
            {
                float e0, o0, e1, o1;
                const int rb = rg * 8;
                float2* pr;
                unpack2(A00, e0, o0); unpack2(A01, e1, o1);
                pr = (float2*)&Pk[(rb+0)*PPITCH + 2*cg]; *pr = make_float2(e0, e1);
                pr = (float2*)&Pk[(rb+1)*PPITCH + 2*cg]; *pr = make_float2(o0, o1);
                unpack2(A10, e0, o0); unpack2(A11, e1, o1);
                pr = (float2*)&Pk[(rb+2)*PPITCH + 2*cg]; *pr = make_float2(e0, e1);
                pr = (float2*)&Pk[(rb+3)*PPITCH + 2*cg]; *pr = make_float2(o0, o1);
                unpack2(A20, e0, o0); unpack2(A21, e1, o1);
                pr = (float2*)&Pk[(rb+4)*PPITCH + 2*cg]; *pr = make_float2(e0, e1);
                pr = (float2*)&Pk[(rb+5)*PPITCH + 2*cg]; *pr = make_float2(o0, o1);
                unpack2(A30, e0, o0); unpack2(A31, e1, o1);
                pr = (float2*)&Pk[(rb+6)*PPITCH + 2*cg]; *pr = make_float2(e0, e1);
                pr = (float2*)&Pk[(rb+7)*PPITCH + 2*cg]; *pr = make_float2(o0, o1);
            }
            __syncthreads();

            // -- epilogue: reduce 4 k-quarters, add G, LSTM update
            {
                const float4 p0 = *(const float4*)&P_s[0*32*PPITCH + er*PPITCH + un*4];
                const float4 p1 = *(const float4*)&P_s[1*32*PPITCH + er*PPITCH + un*4];
                const float4 p2 = *(const float4*)&P_s[2*32*PPITCH + er*PPITCH + un*4];
                const float4 p3 = *(const float4*)&P_s[3*32*PPITCH + er*PPITCH + un*4];
                const float ai = (p0.x + p1.x) + (p2.x + p3.x);
                const float af = (p0.y + p1.y) + (p2.y + p3.y);
                const float ag = (p0.z + p1.z) + (p2.z + p3.z);
                const float ao = (p0.w + p1.w) + (p2.w + p3.w);
                const float iv = sigmf(ai + gi);
                const float fv = sigmf(af + gf);
                const float gv = tanh_fast(ag + gg);
                const float ov = sigmf(ao + go);
                const float cn = fv * creg + iv * gv;
                const float hn = ov * tanh_fast(cn);
                const bool act = (t < len_r);
                creg  = act ? cn : creg;
                hprev = act ? hn : hprev;
                if (act) out[((size_t)eb * Tsz + t) * Hsz + n] = hn;
                hnext[(size_t)eb * Hsz + n] = hprev;
            }
        }
        tile_barrier(bar_cnt, bar_gen);
    }

    hfin[(size_t)eb * Hsz + n] = hprev;
    cfin[(size_t)eb * Hsz + n] = creg;
}

// ---------------------------------------------------------------------------
extern "C" void kernel_launch(void* const* d_in, const int* in_sizes, int n_in,
                              void* d_out, int out_size)
{
    (void)in_sizes; (void)n_in; (void)out_size;
    const float* seq  = (const float*)d_in[0];
    const int*   lens = (const int*)d_in[1];
    const float* Wih  = (const float*)d_in[2];
    const float* Whh  = (const float*)d_in[3];
    const float* bih  = (const float*)d_in[4];
    const float* bhh  = (const float*)d_in[5];

    float* outp = (float*)d_out;
    float* hfin = outp + (size_t)Bsz * Tsz * Hsz;
    float* cfin = hfin + (size_t)Bsz * Hsz;

    const int smem2 = (512 * 64 + 512 * 32 + 4 * 32 * PPITCH) * 4;
    cudaFuncSetAttribute(lstm_steps_kernel,
                         cudaFuncAttributeMaxDynamicSharedMemorySize, smem2);

    // Phase 1: input-gate GEMM -> transposed G[t][j][b]
    dim3 grid1(G4 / 128, Tsz);
    pregemm_kernel<<<grid1, 256>>>(seq, Wih, bih, bhh, lens);

    // Phase 2: persistent recurrence (128 co-resident blocks, btile barriers)
    lstm_steps_kernel<<<128, 512, smem2>>>(Whh, lens, outp, hfin, cfin);
}